// round 2
// baseline (speedup 1.0000x reference)
#include <cuda_runtime.h>
#include <cuda_bf16.h>
#include <math.h>

// Problem constants
#define CHUNKS     8
#define CSIZE      512
#define DIM        4096          // CHUNKS * CSIZE
#define NROWS      16384         // 4 * 4096
#define INV_TEMP   (1.0f / 0.15f)
#define SINK_ITERS 5

// Scratch (device-global: no runtime allocation allowed)
__device__ float g_qlog[CHUNKS * CSIZE * CSIZE];   // 8 MB  sinkhorn working buffer / final Q
__device__ float g_p[CHUNKS * CHUNKS];             // 8x8 chunk perm
__device__ float g_y[(size_t)NROWS * DIM];         // 256 MB mixed activations

// ---------------------------------------------------------------------------
// Sinkhorn on the 8x8 chunk logits: one block, 64 threads.
// ---------------------------------------------------------------------------
__global__ void sinkhorn_chunk_kernel(const float* __restrict__ logits,
                                      float* __restrict__ p_out) {
    __shared__ float s[64];
    int t = threadIdx.x;
    int r = t >> 3;
    int c = t & 7;
    float v = logits[t] * INV_TEMP;

    for (int it = 0; it < SINK_ITERS; ++it) {
        // row logsumexp (over last axis)
        s[t] = v;
        __syncthreads();
        float mx = -1e30f;
        #pragma unroll
        for (int j = 0; j < 8; ++j) mx = fmaxf(mx, s[r * 8 + j]);
        float sm = 0.0f;
        #pragma unroll
        for (int j = 0; j < 8; ++j) sm += expf(s[r * 8 + j] - mx);
        v -= mx + logf(sm);
        __syncthreads();

        // col logsumexp (over axis -2)
        s[t] = v;
        __syncthreads();
        mx = -1e30f;
        #pragma unroll
        for (int j = 0; j < 8; ++j) mx = fmaxf(mx, s[j * 8 + c]);
        sm = 0.0f;
        #pragma unroll
        for (int j = 0; j < 8; ++j) sm += expf(s[j * 8 + c] - mx);
        v -= mx + logf(sm);
        __syncthreads();
    }
    p_out[t] = expf(v);
}

// ---------------------------------------------------------------------------
// Sinkhorn row pass for intra logits: one block per (chunk,row). 512 values.
// First call reads the raw logits and applies 1/T; later calls are in-place.
// ---------------------------------------------------------------------------
__global__ void lse_rows_kernel(const float* __restrict__ in,
                                float* __restrict__ out, float scale) {
    int row = blockIdx.x;                 // 0 .. 8*512-1
    const float* p = in  + (size_t)row * CSIZE;
    float*       q = out + (size_t)row * CSIZE;
    int t = threadIdx.x;                  // 128

    float v[4];
    float mx = -1e30f;
    #pragma unroll
    for (int i = 0; i < 4; ++i) {
        v[i] = p[t + i * 128] * scale;
        mx = fmaxf(mx, v[i]);
    }

    __shared__ float red[128];
    red[t] = mx;
    __syncthreads();
    #pragma unroll
    for (int s2 = 64; s2 > 0; s2 >>= 1) {
        if (t < s2) red[t] = fmaxf(red[t], red[t + s2]);
        __syncthreads();
    }
    mx = red[0];
    __syncthreads();

    float sm = 0.0f;
    #pragma unroll
    for (int i = 0; i < 4; ++i) sm += expf(v[i] - mx);
    red[t] = sm;
    __syncthreads();
    #pragma unroll
    for (int s2 = 64; s2 > 0; s2 >>= 1) {
        if (t < s2) red[t] += red[t + s2];
        __syncthreads();
    }
    float lse = mx + logf(red[0]);

    #pragma unroll
    for (int i = 0; i < 4; ++i) q[t + i * 128] = v[i] - lse;
}

// ---------------------------------------------------------------------------
// Sinkhorn column pass: each thread owns one full column (coalesced across
// threads). Optionally applies exp() on the final pass.
// ---------------------------------------------------------------------------
__global__ void lse_cols_kernel(float* __restrict__ buf, int apply_exp) {
    int chunk = blockIdx.x >> 2;                        // grid = 8*4
    int col   = ((blockIdx.x & 3) << 7) + threadIdx.x;  // 128 threads
    float* base = buf + (size_t)chunk * CSIZE * CSIZE + col;

    float mx = -1e30f;
    #pragma unroll 8
    for (int r = 0; r < CSIZE; ++r) mx = fmaxf(mx, base[(size_t)r * CSIZE]);

    float sm = 0.0f;
    #pragma unroll 8
    for (int r = 0; r < CSIZE; ++r) sm += expf(base[(size_t)r * CSIZE] - mx);

    float lse = mx + logf(sm);

    if (apply_exp) {
        #pragma unroll 8
        for (int r = 0; r < CSIZE; ++r)
            base[(size_t)r * CSIZE] = expf(base[(size_t)r * CSIZE] - lse);
    } else {
        #pragma unroll 8
        for (int r = 0; r < CSIZE; ++r)
            base[(size_t)r * CSIZE] -= lse;
    }
}

// ---------------------------------------------------------------------------
// Chunk mix: y[b, i*512+d] = sum_j P[i,j] * x[b, j*512+d].  float4 vectorized.
// ---------------------------------------------------------------------------
__global__ void mix_kernel(const float* __restrict__ x,
                           float* __restrict__ y,
                           const float* __restrict__ P) {
    __shared__ float p[64];
    if (threadIdx.x < 64) p[threadIdx.x] = P[threadIdx.x];
    __syncthreads();

    int idx = blockIdx.x * blockDim.x + threadIdx.x;   // NROWS * 128 total
    int b  = idx >> 7;
    int d4 = idx & 127;          // float4 index within a 512-wide chunk

    const float4* xb = (const float4*)(x + (size_t)b * DIM) + d4;
    float4*       yb = (float4*)(y + (size_t)b * DIM) + d4;

    float4 xv[8];
    #pragma unroll
    for (int j = 0; j < 8; ++j) xv[j] = xb[(size_t)j * 128];

    #pragma unroll
    for (int i = 0; i < 8; ++i) {
        float4 acc = make_float4(0.f, 0.f, 0.f, 0.f);
        #pragma unroll
        for (int j = 0; j < 8; ++j) {
            float w = p[i * 8 + j];
            acc.x += w * xv[j].x;
            acc.y += w * xv[j].y;
            acc.z += w * xv[j].z;
            acc.w += w * xv[j].w;
        }
        yb[(size_t)i * 128] = acc;
    }
}

// ---------------------------------------------------------------------------
// Per-chunk NT SGEMM: out[m, c*512+n] = sum_k Y[m, c*512+k] * Q_c[n, k]
// 128x128x8 block tile, 256 threads, 8x8 microtile (split 4+4 to reduce
// shared-memory bank conflicts).
// ---------------------------------------------------------------------------
#define BM 128
#define BN 128
#define BK 8

__global__ __launch_bounds__(256, 2)
void sgemm_kernel(const float* __restrict__ Y,
                  const float* __restrict__ Q,
                  float* __restrict__ out) {
    int c  = blockIdx.z;
    int m0 = blockIdx.y * BM;
    int n0 = blockIdx.x * BN;

    const float* A = Y + (size_t)c * CSIZE;                 // row stride DIM
    const float* B = Q + (size_t)c * CSIZE * CSIZE;         // [512][512]

    __shared__ float As[BK][BM];
    __shared__ float Bs[BK][BN];

    int tid = threadIdx.x;       // 256
    int lr = tid >> 1;           // 0..127 (tile row for loads)
    int lc = (tid & 1) << 2;     // 0 or 4 (k offset for loads)

    int tx = tid & 15;           // 0..15
    int ty = tid >> 4;           // 0..15

    float acc[8][8];
    #pragma unroll
    for (int i = 0; i < 8; ++i)
        #pragma unroll
        for (int j = 0; j < 8; ++j) acc[i][j] = 0.0f;

    const float* aptr = A + (size_t)(m0 + lr) * DIM + lc;
    const float* bptr = B + (size_t)(n0 + lr) * CSIZE + lc;

    for (int k0 = 0; k0 < CSIZE; k0 += BK) {
        float4 a4 = *(const float4*)(aptr + k0);
        float4 b4 = *(const float4*)(bptr + k0);
        As[lc + 0][lr] = a4.x; As[lc + 1][lr] = a4.y;
        As[lc + 2][lr] = a4.z; As[lc + 3][lr] = a4.w;
        Bs[lc + 0][lr] = b4.x; Bs[lc + 1][lr] = b4.y;
        Bs[lc + 2][lr] = b4.z; Bs[lc + 3][lr] = b4.w;
        __syncthreads();

        #pragma unroll
        for (int kk = 0; kk < BK; ++kk) {
            float4 a0 = *(const float4*)&As[kk][ty * 4];
            float4 a1 = *(const float4*)&As[kk][64 + ty * 4];
            float4 b0 = *(const float4*)&Bs[kk][tx * 4];
            float4 b1 = *(const float4*)&Bs[kk][64 + tx * 4];
            float af[8] = {a0.x, a0.y, a0.z, a0.w, a1.x, a1.y, a1.z, a1.w};
            float bf[8] = {b0.x, b0.y, b0.z, b0.w, b1.x, b1.y, b1.z, b1.w};
            #pragma unroll
            for (int i = 0; i < 8; ++i)
                #pragma unroll
                for (int j = 0; j < 8; ++j)
                    acc[i][j] = fmaf(af[i], bf[j], acc[i][j]);
        }
        __syncthreads();
    }

    // Write back: rows {ty*4..+3, 64+ty*4..+3}, cols {tx*4..+3, 64+tx*4..+3}
    #pragma unroll
    for (int i = 0; i < 8; ++i) {
        int m = m0 + ((i < 4) ? (ty * 4 + i) : (64 + ty * 4 + i - 4));
        float* orow = out + (size_t)m * DIM + c * CSIZE + n0;
        float4 v0 = make_float4(acc[i][0], acc[i][1], acc[i][2], acc[i][3]);
        float4 v1 = make_float4(acc[i][4], acc[i][5], acc[i][6], acc[i][7]);
        *(float4*)(orow + tx * 4)       = v0;
        *(float4*)(orow + 64 + tx * 4)  = v1;
    }
}

// ---------------------------------------------------------------------------
// Launch
// ---------------------------------------------------------------------------
extern "C" void kernel_launch(void* const* d_in, const int* in_sizes, int n_in,
                              void* d_out, int out_size) {
    const float* x            = (const float*)d_in[0];
    const float* chunk_logits = (const float*)d_in[1];
    const float* intra_logits = (const float*)d_in[2];
    float*       out          = (float*)d_out;

    float* qlog; cudaGetSymbolAddress((void**)&qlog, g_qlog);
    float* p;    cudaGetSymbolAddress((void**)&p,    g_p);
    float* y;    cudaGetSymbolAddress((void**)&y,    g_y);

    // 1) 8x8 chunk sinkhorn
    sinkhorn_chunk_kernel<<<1, 64>>>(chunk_logits, p);

    // 2) intra sinkhorn: 5x (row-norm, col-norm); exp fused into final col pass
    lse_rows_kernel<<<CHUNKS * CSIZE, 128>>>(intra_logits, qlog, INV_TEMP);
    lse_cols_kernel<<<CHUNKS * 4, 128>>>(qlog, 0);
    for (int it = 1; it < SINK_ITERS; ++it) {
        lse_rows_kernel<<<CHUNKS * CSIZE, 128>>>(qlog, qlog, 1.0f);
        lse_cols_kernel<<<CHUNKS * 4, 128>>>(qlog, (it == SINK_ITERS - 1) ? 1 : 0);
    }

    // 3) chunk mix: y = P @ x (per (b,d))
    mix_kernel<<<(NROWS * 128) / 256, 256>>>(x, y, p);

    // 4) per-chunk GEMM: out = Y_c @ Q_c^T
    dim3 grid(CSIZE / BN, NROWS / BM, CHUNKS);
    sgemm_kernel<<<grid, 256>>>(y, qlog, out);
}

// round 4
// speedup vs baseline: 1.8780x; 1.8780x over previous
#include <cuda_runtime.h>
#include <cuda_bf16.h>
#include <mma.h>
#include <math.h>
#include <stdint.h>

using namespace nvcuda;

// Problem constants
#define CHUNKS     8
#define CSIZE      512
#define DIM        4096
#define NROWS      16384
#define INV_TEMP   (1.0f / 0.15f)
#define SINK_ITERS 5

// Scratch (device globals — no runtime allocation allowed)
__device__ float         g_qlog[CHUNKS * CSIZE * CSIZE];       // 8 MB sinkhorn buffer
__device__ float         g_p[64];                              // 8x8 chunk perm
__device__ __nv_bfloat16 g_qhi[CHUNKS * CSIZE * CSIZE];        // 4 MB
__device__ __nv_bfloat16 g_qlo[CHUNKS * CSIZE * CSIZE];        // 4 MB
__device__ __nv_bfloat16 g_yhi[(size_t)NROWS * DIM];           // 128 MB
__device__ __nv_bfloat16 g_ylo[(size_t)NROWS * DIM];           // 128 MB

// ---------------------------------------------------------------------------
// Sinkhorn on 8x8 chunk logits
// ---------------------------------------------------------------------------
__global__ void sinkhorn_chunk_kernel(const float* __restrict__ logits,
                                      float* __restrict__ p_out) {
    __shared__ float s[64];
    int t = threadIdx.x;
    int r = t >> 3;
    int c = t & 7;
    float v = logits[t] * INV_TEMP;

    for (int it = 0; it < SINK_ITERS; ++it) {
        s[t] = v;
        __syncthreads();
        float mx = -1e30f;
        #pragma unroll
        for (int j = 0; j < 8; ++j) mx = fmaxf(mx, s[r * 8 + j]);
        float sm = 0.0f;
        #pragma unroll
        for (int j = 0; j < 8; ++j) sm += expf(s[r * 8 + j] - mx);
        v -= mx + logf(sm);
        __syncthreads();

        s[t] = v;
        __syncthreads();
        mx = -1e30f;
        #pragma unroll
        for (int j = 0; j < 8; ++j) mx = fmaxf(mx, s[j * 8 + c]);
        sm = 0.0f;
        #pragma unroll
        for (int j = 0; j < 8; ++j) sm += expf(s[j * 8 + c] - mx);
        v -= mx + logf(sm);
        __syncthreads();
    }
    p_out[t] = expf(v);
}

// ---------------------------------------------------------------------------
// Row LSE pass (over last axis). Block per row, 128 threads.
// ---------------------------------------------------------------------------
__global__ void lse_rows_kernel(const float* __restrict__ in,
                                float* __restrict__ out, float scale) {
    int row = blockIdx.x;
    const float* p = in  + (size_t)row * CSIZE;
    float*       q = out + (size_t)row * CSIZE;
    int t = threadIdx.x;

    float v[4];
    float mx = -1e30f;
    #pragma unroll
    for (int i = 0; i < 4; ++i) {
        v[i] = p[t + i * 128] * scale;
        mx = fmaxf(mx, v[i]);
    }

    __shared__ float red[128];
    red[t] = mx;
    __syncthreads();
    #pragma unroll
    for (int s2 = 64; s2 > 0; s2 >>= 1) {
        if (t < s2) red[t] = fmaxf(red[t], red[t + s2]);
        __syncthreads();
    }
    mx = red[0];
    __syncthreads();

    float sm = 0.0f;
    #pragma unroll
    for (int i = 0; i < 4; ++i) sm += expf(v[i] - mx);
    red[t] = sm;
    __syncthreads();
    #pragma unroll
    for (int s2 = 64; s2 > 0; s2 >>= 1) {
        if (t < s2) red[t] += red[t + s2];
        __syncthreads();
    }
    float lse = mx + logf(red[0]);

    #pragma unroll
    for (int i = 0; i < 4; ++i) q[t + i * 128] = v[i] - lse;
}

// ---------------------------------------------------------------------------
// Column LSE pass (over axis -2). Grid = 8 chunks * 16 colgroups, 256 thr.
// ---------------------------------------------------------------------------
__global__ void lse_cols_kernel(float* __restrict__ buf, int apply_exp) {
    int chunk = blockIdx.x >> 4;
    int colbase = (blockIdx.x & 15) * 32;
    int t = threadIdx.x;
    int col = t & 31;
    int rg  = t >> 5;                 // 0..7
    float* base = buf + (size_t)chunk * CSIZE * CSIZE + colbase + col;

    __shared__ float red[8][32];

    float mx = -1e30f;
    for (int r = rg; r < CSIZE; r += 8) mx = fmaxf(mx, base[(size_t)r * CSIZE]);
    red[rg][col] = mx;
    __syncthreads();
    if (rg == 0) {
        float m = red[0][col];
        #pragma unroll
        for (int j = 1; j < 8; ++j) m = fmaxf(m, red[j][col]);
        red[0][col] = m;
    }
    __syncthreads();
    mx = red[0][col];
    __syncthreads();

    float sm = 0.0f;
    for (int r = rg; r < CSIZE; r += 8) sm += expf(base[(size_t)r * CSIZE] - mx);
    red[rg][col] = sm;
    __syncthreads();
    if (rg == 0) {
        float s = red[0][col];
        #pragma unroll
        for (int j = 1; j < 8; ++j) s += red[j][col];
        red[0][col] = s;
    }
    __syncthreads();
    float lse = mx + logf(red[0][col]);

    if (apply_exp) {
        for (int r = rg; r < CSIZE; r += 8)
            base[(size_t)r * CSIZE] = expf(base[(size_t)r * CSIZE] - lse);
    } else {
        for (int r = rg; r < CSIZE; r += 8)
            base[(size_t)r * CSIZE] -= lse;
    }
}

// ---------------------------------------------------------------------------
// Split Q (fp32) -> hi/lo bf16
// ---------------------------------------------------------------------------
__global__ void qsplit_kernel(const float* __restrict__ q,
                              __nv_bfloat16* __restrict__ qhi,
                              __nv_bfloat16* __restrict__ qlo) {
    int i = blockIdx.x * blockDim.x + threadIdx.x;  // float4 index
    float4 v = ((const float4*)q)[i];
    float f[4] = {v.x, v.y, v.z, v.w};
    __nv_bfloat162 h01, h23, l01, l23;
    __nv_bfloat16 h, l;

    h = __float2bfloat16(f[0]); l = __float2bfloat16(f[0] - __bfloat162float(h));
    h01.x = h; l01.x = l;
    h = __float2bfloat16(f[1]); l = __float2bfloat16(f[1] - __bfloat162float(h));
    h01.y = h; l01.y = l;
    h = __float2bfloat16(f[2]); l = __float2bfloat16(f[2] - __bfloat162float(h));
    h23.x = h; l23.x = l;
    h = __float2bfloat16(f[3]); l = __float2bfloat16(f[3] - __bfloat162float(h));
    h23.y = h; l23.y = l;

    ((__nv_bfloat162*)qhi)[2 * i]     = h01;
    ((__nv_bfloat162*)qhi)[2 * i + 1] = h23;
    ((__nv_bfloat162*)qlo)[2 * i]     = l01;
    ((__nv_bfloat162*)qlo)[2 * i + 1] = l23;
}

// ---------------------------------------------------------------------------
// Chunk mix producing split bf16: y = P @ x per (b, d)
// ---------------------------------------------------------------------------
__global__ void mix_split_kernel(const float* __restrict__ x,
                                 __nv_bfloat16* __restrict__ yhi,
                                 __nv_bfloat16* __restrict__ ylo,
                                 const float* __restrict__ P) {
    __shared__ float p[64];
    if (threadIdx.x < 64) p[threadIdx.x] = P[threadIdx.x];
    __syncthreads();

    int idx = blockIdx.x * blockDim.x + threadIdx.x;
    int b  = idx >> 7;
    int d4 = idx & 127;

    const float4* xb = (const float4*)(x + (size_t)b * DIM) + d4;

    float4 xv[8];
    #pragma unroll
    for (int j = 0; j < 8; ++j) xv[j] = xb[(size_t)j * 128];

    #pragma unroll
    for (int i = 0; i < 8; ++i) {
        float4 acc = make_float4(0.f, 0.f, 0.f, 0.f);
        #pragma unroll
        for (int j = 0; j < 8; ++j) {
            float w = p[i * 8 + j];
            acc.x += w * xv[j].x;
            acc.y += w * xv[j].y;
            acc.z += w * xv[j].z;
            acc.w += w * xv[j].w;
        }
        float f[4] = {acc.x, acc.y, acc.z, acc.w};
        __nv_bfloat162 h01, h23, l01, l23;
        __nv_bfloat16 h, l;
        h = __float2bfloat16(f[0]); l = __float2bfloat16(f[0] - __bfloat162float(h));
        h01.x = h; l01.x = l;
        h = __float2bfloat16(f[1]); l = __float2bfloat16(f[1] - __bfloat162float(h));
        h01.y = h; l01.y = l;
        h = __float2bfloat16(f[2]); l = __float2bfloat16(f[2] - __bfloat162float(h));
        h23.x = h; l23.x = l;
        h = __float2bfloat16(f[3]); l = __float2bfloat16(f[3] - __bfloat162float(h));
        h23.y = h; l23.y = l;

        size_t e = (size_t)b * DIM + (size_t)i * CSIZE + (size_t)d4 * 4;  // even
        ((__nv_bfloat162*)yhi)[e >> 1]       = h01;
        ((__nv_bfloat162*)yhi)[(e >> 1) + 1] = h23;
        ((__nv_bfloat162*)ylo)[e >> 1]       = l01;
        ((__nv_bfloat162*)ylo)[(e >> 1) + 1] = l23;
    }
}

// ---------------------------------------------------------------------------
// WMMA (HMMA) GEMM: per CTA 128x128 tile over K = 3*512 (hi*hi + hi*lo + lo*hi)
// Double-buffered cp.async, 8 warps (2M x 4N), warp tile 64x32.
// ---------------------------------------------------------------------------
#define KTILE   32
#define LDS_PAD 40          // padded row stride (elems): 80 B, multiple of 16 B
#define NKITER  48          // 3 segments * 512 / 32

__device__ __forceinline__ void cp16(uint32_t dst, const void* src) {
    asm volatile("cp.async.cg.shared.global [%0], [%1], 16;" :: "r"(dst), "l"(src));
}

__global__ __launch_bounds__(256, 2)
void wmma_gemm_kernel(const __nv_bfloat16* __restrict__ yhi,
                      const __nv_bfloat16* __restrict__ ylo,
                      const __nv_bfloat16* __restrict__ qhi,
                      const __nv_bfloat16* __restrict__ qlo,
                      float* __restrict__ out) {
    __shared__ __nv_bfloat16 sA[2][128 * LDS_PAD];
    __shared__ __nv_bfloat16 sB[2][128 * LDS_PAD];

    const int c  = blockIdx.z;
    const int m0 = blockIdx.y * 128;
    const int n0 = blockIdx.x * 128;
    const int tid = threadIdx.x;
    const int wid = tid >> 5;
    const int wm  = wid & 1;       // 0..1  -> 64-row slab
    const int wn  = wid >> 1;      // 0..3  -> 32-col slab

    wmma::fragment<wmma::accumulator, 16, 16, 16, float> acc[4][2];
    #pragma unroll
    for (int i = 0; i < 4; ++i)
        #pragma unroll
        for (int j = 0; j < 2; ++j) wmma::fill_fragment(acc[i][j], 0.0f);

    // per-thread load assignment: 512 x 16B chunks per tile, 2 per thread
    const int r0  = (tid + 0)   >> 2;   // row for unit 0
    const int cb0 = (tid + 0)   & 3;
    const int r1  = (tid + 256) >> 2;   // row for unit 1
    const int cb1 = (tid + 256) & 3;

    uint32_t sA0[2], sA1[2], sB0[2], sB1[2];
    #pragma unroll
    for (int b = 0; b < 2; ++b) {
        sA0[b] = (uint32_t)__cvta_generic_to_shared(&sA[b][r0 * LDS_PAD + cb0 * 8]);
        sA1[b] = (uint32_t)__cvta_generic_to_shared(&sA[b][r1 * LDS_PAD + cb1 * 8]);
        sB0[b] = (uint32_t)__cvta_generic_to_shared(&sB[b][r0 * LDS_PAD + cb0 * 8]);
        sB1[b] = (uint32_t)__cvta_generic_to_shared(&sB[b][r1 * LDS_PAD + cb1 * 8]);
    }

    auto issue_loads = [&](int i, int buf) {
        int seg = i >> 4;
        int kk  = (i & 15) << 5;
        const __nv_bfloat16* A = ((seg < 2) ? yhi : ylo)
                                 + (size_t)m0 * DIM + (size_t)c * CSIZE + kk;
        const __nv_bfloat16* B = ((seg == 1) ? qlo : qhi)
                                 + (size_t)c * CSIZE * CSIZE + (size_t)n0 * CSIZE + kk;
        cp16(sA0[buf], A + (size_t)r0 * DIM + cb0 * 8);
        cp16(sA1[buf], A + (size_t)r1 * DIM + cb1 * 8);
        cp16(sB0[buf], B + (size_t)r0 * CSIZE + cb0 * 8);
        cp16(sB1[buf], B + (size_t)r1 * CSIZE + cb1 * 8);
        asm volatile("cp.async.commit_group;" ::: "memory");
    };

    issue_loads(0, 0);

    for (int i = 0; i < NKITER; ++i) {
        int s = i & 1;
        asm volatile("cp.async.wait_group 0;" ::: "memory");
        __syncthreads();

        if (i < NKITER - 1) issue_loads(i + 1, s ^ 1);

        #pragma unroll
        for (int k2 = 0; k2 < 2; ++k2) {
            wmma::fragment<wmma::matrix_a, 16, 16, 16, __nv_bfloat16, wmma::row_major> af[4];
            wmma::fragment<wmma::matrix_b, 16, 16, 16, __nv_bfloat16, wmma::col_major> bf[2];
            #pragma unroll
            for (int mi = 0; mi < 4; ++mi)
                wmma::load_matrix_sync(af[mi],
                    &sA[s][(wm * 64 + mi * 16) * LDS_PAD + k2 * 16], LDS_PAD);
            #pragma unroll
            for (int nj = 0; nj < 2; ++nj)
                wmma::load_matrix_sync(bf[nj],
                    &sB[s][(wn * 32 + nj * 16) * LDS_PAD + k2 * 16], LDS_PAD);
            #pragma unroll
            for (int mi = 0; mi < 4; ++mi)
                #pragma unroll
                for (int nj = 0; nj < 2; ++nj)
                    wmma::mma_sync(acc[mi][nj], af[mi], bf[nj], acc[mi][nj]);
        }
        __syncthreads();
    }

    // epilogue: direct store to out
    #pragma unroll
    for (int mi = 0; mi < 4; ++mi) {
        #pragma unroll
        for (int nj = 0; nj < 2; ++nj) {
            float* dst = out + (size_t)(m0 + wm * 64 + mi * 16) * DIM
                             + (size_t)c * CSIZE + n0 + wn * 32 + nj * 16;
            wmma::store_matrix_sync(dst, acc[mi][nj], DIM, wmma::mem_row_major);
        }
    }
}

// ---------------------------------------------------------------------------
// Launch
// ---------------------------------------------------------------------------
extern "C" void kernel_launch(void* const* d_in, const int* in_sizes, int n_in,
                              void* d_out, int out_size) {
    const float* x            = (const float*)d_in[0];
    const float* chunk_logits = (const float*)d_in[1];
    const float* intra_logits = (const float*)d_in[2];
    float*       out          = (float*)d_out;

    float* qlog;          cudaGetSymbolAddress((void**)&qlog, g_qlog);
    float* p;             cudaGetSymbolAddress((void**)&p,    g_p);
    __nv_bfloat16* qhi;   cudaGetSymbolAddress((void**)&qhi,  g_qhi);
    __nv_bfloat16* qlo;   cudaGetSymbolAddress((void**)&qlo,  g_qlo);
    __nv_bfloat16* yhi;   cudaGetSymbolAddress((void**)&yhi,  g_yhi);
    __nv_bfloat16* ylo;   cudaGetSymbolAddress((void**)&ylo,  g_ylo);

    // 1) 8x8 chunk sinkhorn
    sinkhorn_chunk_kernel<<<1, 64>>>(chunk_logits, p);

    // 2) intra sinkhorn (5x row+col), exp fused into final col pass
    lse_rows_kernel<<<CHUNKS * CSIZE, 128>>>(intra_logits, qlog, INV_TEMP);
    lse_cols_kernel<<<CHUNKS * 16, 256>>>(qlog, 0);
    for (int it = 1; it < SINK_ITERS; ++it) {
        lse_rows_kernel<<<CHUNKS * CSIZE, 128>>>(qlog, qlog, 1.0f);
        lse_cols_kernel<<<CHUNKS * 16, 256>>>(qlog, (it == SINK_ITERS - 1) ? 1 : 0);
    }

    // 3) Q split into bf16 hi/lo
    qsplit_kernel<<<(CHUNKS * CSIZE * CSIZE / 4) / 256, 256>>>(qlog, qhi, qlo);

    // 4) chunk mix -> split bf16 Y
    mix_split_kernel<<<(NROWS * 128) / 256, 256>>>(x, yhi, ylo, p);

    // 5) tensor-core GEMM: out = Yhi Qhi^T + Yhi Qlo^T + Ylo Qhi^T
    dim3 grid(4, NROWS / 128, CHUNKS);
    wmma_gemm_kernel<<<grid, 256>>>(yhi, ylo, qhi, qlo, out);
}

// round 5
// speedup vs baseline: 4.8202x; 2.5667x over previous
#include <cuda_runtime.h>
#include <cuda_fp16.h>
#include <mma.h>
#include <math.h>
#include <stdint.h>

using namespace nvcuda;

// Problem constants
#define CHUNKS     8
#define CSIZE      512
#define DIM        4096
#define NROWS      16384
#define INV_TEMP   (1.0f / 0.15f)
#define SINK_ITERS 5

// Scratch (device globals — no runtime allocation allowed)
__device__ float  g_qlog[CHUNKS * CSIZE * CSIZE];      // 8 MB sinkhorn buffer
__device__ float  g_p[64];                             // 8x8 chunk perm
__device__ __half g_qh[CHUNKS * CSIZE * CSIZE];        // 4 MB   Q fp16
__device__ __half g_yh[(size_t)NROWS * DIM];           // 128 MB Y fp16

// ---------------------------------------------------------------------------
// Sinkhorn on 8x8 chunk logits
// ---------------------------------------------------------------------------
__global__ void sinkhorn_chunk_kernel(const float* __restrict__ logits,
                                      float* __restrict__ p_out) {
    __shared__ float s[64];
    int t = threadIdx.x;
    int r = t >> 3;
    int c = t & 7;
    float v = logits[t] * INV_TEMP;

    for (int it = 0; it < SINK_ITERS; ++it) {
        s[t] = v;
        __syncthreads();
        float mx = -1e30f;
        #pragma unroll
        for (int j = 0; j < 8; ++j) mx = fmaxf(mx, s[r * 8 + j]);
        float sm = 0.0f;
        #pragma unroll
        for (int j = 0; j < 8; ++j) sm += expf(s[r * 8 + j] - mx);
        v -= mx + logf(sm);
        __syncthreads();

        s[t] = v;
        __syncthreads();
        mx = -1e30f;
        #pragma unroll
        for (int j = 0; j < 8; ++j) mx = fmaxf(mx, s[j * 8 + c]);
        sm = 0.0f;
        #pragma unroll
        for (int j = 0; j < 8; ++j) sm += expf(s[j * 8 + c] - mx);
        v -= mx + logf(sm);
        __syncthreads();
    }
    p_out[t] = expf(v);
}

// ---------------------------------------------------------------------------
// Row LSE pass (over last axis). Block per row, 128 threads.
// ---------------------------------------------------------------------------
__global__ void lse_rows_kernel(const float* __restrict__ in,
                                float* __restrict__ out, float scale) {
    int row = blockIdx.x;
    const float* p = in  + (size_t)row * CSIZE;
    float*       q = out + (size_t)row * CSIZE;
    int t = threadIdx.x;

    float v[4];
    float mx = -1e30f;
    #pragma unroll
    for (int i = 0; i < 4; ++i) {
        v[i] = p[t + i * 128] * scale;
        mx = fmaxf(mx, v[i]);
    }

    __shared__ float red[128];
    red[t] = mx;
    __syncthreads();
    #pragma unroll
    for (int s2 = 64; s2 > 0; s2 >>= 1) {
        if (t < s2) red[t] = fmaxf(red[t], red[t + s2]);
        __syncthreads();
    }
    mx = red[0];
    __syncthreads();

    float sm = 0.0f;
    #pragma unroll
    for (int i = 0; i < 4; ++i) sm += expf(v[i] - mx);
    red[t] = sm;
    __syncthreads();
    #pragma unroll
    for (int s2 = 64; s2 > 0; s2 >>= 1) {
        if (t < s2) red[t] += red[t + s2];
        __syncthreads();
    }
    float lse = mx + logf(red[0]);

    #pragma unroll
    for (int i = 0; i < 4; ++i) q[t + i * 128] = v[i] - lse;
}

// ---------------------------------------------------------------------------
// Column LSE pass (over axis -2). Grid = 8 chunks * 16 colgroups, 256 thr.
// Final pass (apply_exp) writes exp(q - lse) as fp16 into qh.
// ---------------------------------------------------------------------------
__global__ void lse_cols_kernel(float* __restrict__ buf,
                                __half* __restrict__ qh, int apply_exp) {
    int chunk = blockIdx.x >> 4;
    int colbase = (blockIdx.x & 15) * 32;
    int t = threadIdx.x;
    int col = t & 31;
    int rg  = t >> 5;                 // 0..7
    size_t base_i = (size_t)chunk * CSIZE * CSIZE + colbase + col;
    float* base = buf + base_i;

    __shared__ float red[8][32];

    float mx = -1e30f;
    for (int r = rg; r < CSIZE; r += 8) mx = fmaxf(mx, base[(size_t)r * CSIZE]);
    red[rg][col] = mx;
    __syncthreads();
    if (rg == 0) {
        float m = red[0][col];
        #pragma unroll
        for (int j = 1; j < 8; ++j) m = fmaxf(m, red[j][col]);
        red[0][col] = m;
    }
    __syncthreads();
    mx = red[0][col];
    __syncthreads();

    float sm = 0.0f;
    for (int r = rg; r < CSIZE; r += 8) sm += expf(base[(size_t)r * CSIZE] - mx);
    red[rg][col] = sm;
    __syncthreads();
    if (rg == 0) {
        float s = red[0][col];
        #pragma unroll
        for (int j = 1; j < 8; ++j) s += red[j][col];
        red[0][col] = s;
    }
    __syncthreads();
    float lse = mx + logf(red[0][col]);

    if (apply_exp) {
        __half* qbase = qh + base_i;
        for (int r = rg; r < CSIZE; r += 8)
            qbase[(size_t)r * CSIZE] =
                __float2half(expf(base[(size_t)r * CSIZE] - lse));
    } else {
        for (int r = rg; r < CSIZE; r += 8)
            base[(size_t)r * CSIZE] -= lse;
    }
}

// ---------------------------------------------------------------------------
// Chunk mix producing fp16: y = P @ x per (b, d)
// ---------------------------------------------------------------------------
__global__ void mix_half_kernel(const float* __restrict__ x,
                                __half* __restrict__ yh,
                                const float* __restrict__ P) {
    __shared__ float p[64];
    if (threadIdx.x < 64) p[threadIdx.x] = P[threadIdx.x];
    __syncthreads();

    int idx = blockIdx.x * blockDim.x + threadIdx.x;
    int b  = idx >> 7;
    int d4 = idx & 127;

    const float4* xb = (const float4*)(x + (size_t)b * DIM) + d4;

    float4 xv[8];
    #pragma unroll
    for (int j = 0; j < 8; ++j) xv[j] = xb[(size_t)j * 128];

    #pragma unroll
    for (int i = 0; i < 8; ++i) {
        float4 acc = make_float4(0.f, 0.f, 0.f, 0.f);
        #pragma unroll
        for (int j = 0; j < 8; ++j) {
            float w = p[i * 8 + j];
            acc.x += w * xv[j].x;
            acc.y += w * xv[j].y;
            acc.z += w * xv[j].z;
            acc.w += w * xv[j].w;
        }
        __half2 h01 = __floats2half2_rn(acc.x, acc.y);
        __half2 h23 = __floats2half2_rn(acc.z, acc.w);
        size_t e = (size_t)b * DIM + (size_t)i * CSIZE + (size_t)d4 * 4;  // even
        ((__half2*)yh)[e >> 1]       = h01;
        ((__half2*)yh)[(e >> 1) + 1] = h23;
    }
}

// ---------------------------------------------------------------------------
// WMMA (HMMA) GEMM, fp16 in / fp32 accum: per CTA 128x128 tile, K = 512.
// Double-buffered cp.async, 8 warps (2M x 4N), warp tile 64x32.
// ---------------------------------------------------------------------------
#define KTILE   32
#define LDS_PAD 40          // padded row stride (elems): 80 B, multiple of 16 B
#define NKITER  16          // 512 / 32

__device__ __forceinline__ void cp16(uint32_t dst, const void* src) {
    asm volatile("cp.async.cg.shared.global [%0], [%1], 16;" :: "r"(dst), "l"(src));
}

__global__ __launch_bounds__(256, 2)
void wmma_gemm_kernel(const __half* __restrict__ yh,
                      const __half* __restrict__ qh,
                      float* __restrict__ out) {
    __shared__ __half sA[2][128 * LDS_PAD];
    __shared__ __half sB[2][128 * LDS_PAD];

    const int c  = blockIdx.z;
    const int m0 = blockIdx.y * 128;
    const int n0 = blockIdx.x * 128;
    const int tid = threadIdx.x;
    const int wid = tid >> 5;
    const int wm  = wid & 1;       // 0..1  -> 64-row slab
    const int wn  = wid >> 1;      // 0..3  -> 32-col slab

    wmma::fragment<wmma::accumulator, 16, 16, 16, float> acc[4][2];
    #pragma unroll
    for (int i = 0; i < 4; ++i)
        #pragma unroll
        for (int j = 0; j < 2; ++j) wmma::fill_fragment(acc[i][j], 0.0f);

    // per-thread load assignment: 512 x 16B chunks per tile, 2 per thread
    const int r0  = (tid + 0)   >> 2;
    const int cb0 = (tid + 0)   & 3;
    const int r1  = (tid + 256) >> 2;
    const int cb1 = (tid + 256) & 3;

    uint32_t sA0[2], sA1[2], sB0[2], sB1[2];
    #pragma unroll
    for (int b = 0; b < 2; ++b) {
        sA0[b] = (uint32_t)__cvta_generic_to_shared(&sA[b][r0 * LDS_PAD + cb0 * 8]);
        sA1[b] = (uint32_t)__cvta_generic_to_shared(&sA[b][r1 * LDS_PAD + cb1 * 8]);
        sB0[b] = (uint32_t)__cvta_generic_to_shared(&sB[b][r0 * LDS_PAD + cb0 * 8]);
        sB1[b] = (uint32_t)__cvta_generic_to_shared(&sB[b][r1 * LDS_PAD + cb1 * 8]);
    }

    const __half* Abase = yh + (size_t)m0 * DIM + (size_t)c * CSIZE;
    const __half* Bbase = qh + (size_t)c * CSIZE * CSIZE + (size_t)n0 * CSIZE;

    auto issue_loads = [&](int i, int buf) {
        int kk = i << 5;
        const __half* A = Abase + kk;
        const __half* B = Bbase + kk;
        cp16(sA0[buf], A + (size_t)r0 * DIM + cb0 * 8);
        cp16(sA1[buf], A + (size_t)r1 * DIM + cb1 * 8);
        cp16(sB0[buf], B + (size_t)r0 * CSIZE + cb0 * 8);
        cp16(sB1[buf], B + (size_t)r1 * CSIZE + cb1 * 8);
        asm volatile("cp.async.commit_group;" ::: "memory");
    };

    issue_loads(0, 0);

    for (int i = 0; i < NKITER; ++i) {
        int s = i & 1;
        asm volatile("cp.async.wait_group 0;" ::: "memory");
        __syncthreads();

        if (i < NKITER - 1) issue_loads(i + 1, s ^ 1);

        #pragma unroll
        for (int k2 = 0; k2 < 2; ++k2) {
            wmma::fragment<wmma::matrix_a, 16, 16, 16, __half, wmma::row_major> af[4];
            wmma::fragment<wmma::matrix_b, 16, 16, 16, __half, wmma::col_major> bf[2];
            #pragma unroll
            for (int mi = 0; mi < 4; ++mi)
                wmma::load_matrix_sync(af[mi],
                    &sA[s][(wm * 64 + mi * 16) * LDS_PAD + k2 * 16], LDS_PAD);
            #pragma unroll
            for (int nj = 0; nj < 2; ++nj)
                wmma::load_matrix_sync(bf[nj],
                    &sB[s][(wn * 32 + nj * 16) * LDS_PAD + k2 * 16], LDS_PAD);
            #pragma unroll
            for (int mi = 0; mi < 4; ++mi)
                #pragma unroll
                for (int nj = 0; nj < 2; ++nj)
                    wmma::mma_sync(acc[mi][nj], af[mi], bf[nj], acc[mi][nj]);
        }
        __syncthreads();
    }

    // epilogue: direct store to out
    #pragma unroll
    for (int mi = 0; mi < 4; ++mi) {
        #pragma unroll
        for (int nj = 0; nj < 2; ++nj) {
            float* dst = out + (size_t)(m0 + wm * 64 + mi * 16) * DIM
                             + (size_t)c * CSIZE + n0 + wn * 32 + nj * 16;
            wmma::store_matrix_sync(dst, acc[mi][nj], DIM, wmma::mem_row_major);
        }
    }
}

// ---------------------------------------------------------------------------
// Launch
// ---------------------------------------------------------------------------
extern "C" void kernel_launch(void* const* d_in, const int* in_sizes, int n_in,
                              void* d_out, int out_size) {
    const float* x            = (const float*)d_in[0];
    const float* chunk_logits = (const float*)d_in[1];
    const float* intra_logits = (const float*)d_in[2];
    float*       out          = (float*)d_out;

    float*  qlog; cudaGetSymbolAddress((void**)&qlog, g_qlog);
    float*  p;    cudaGetSymbolAddress((void**)&p,    g_p);
    __half* qh;   cudaGetSymbolAddress((void**)&qh,   g_qh);
    __half* yh;   cudaGetSymbolAddress((void**)&yh,   g_yh);

    // 1) 8x8 chunk sinkhorn
    sinkhorn_chunk_kernel<<<1, 64>>>(chunk_logits, p);

    // 2) intra sinkhorn (5x row+col); exp + fp16 cast fused into final col pass
    lse_rows_kernel<<<CHUNKS * CSIZE, 128>>>(intra_logits, qlog, INV_TEMP);
    lse_cols_kernel<<<CHUNKS * 16, 256>>>(qlog, qh, 0);
    for (int it = 1; it < SINK_ITERS; ++it) {
        lse_rows_kernel<<<CHUNKS * CSIZE, 128>>>(qlog, qlog, 1.0f);
        lse_cols_kernel<<<CHUNKS * 16, 256>>>(qlog, qh, (it == SINK_ITERS - 1) ? 1 : 0);
    }

    // 3) chunk mix -> fp16 Y
    mix_half_kernel<<<(NROWS * 128) / 256, 256>>>(x, yh, p);

    // 4) tensor-core GEMM (fp16 in, fp32 accum): out = Y Q^T per chunk
    dim3 grid(4, NROWS / 128, CHUNKS);
    wmma_gemm_kernel<<<grid, 256>>>(yh, qh, out);
}